// round 8
// baseline (speedup 1.0000x reference)
#include <cuda_runtime.h>
#include <cstdint>
#include <cstddef>

#define HIDDIM 1024
#define NHEADS 16
#define MEMQ   512
#define LWIN   2048
#define KVLEN  2560
#define DH     64
#define NBATCH 8
#define BHTOT  128
#define QTILE  128

// ---------------- scratch ----------------
static __device__ float g_q  [(size_t)BHTOT * MEMQ  * DH];
static __device__ float g_k  [(size_t)BHTOT * KVLEN * DH];
static __device__ float g_v  [(size_t)BHTOT * KVLEN * DH];
static __device__ float g_peT[(size_t)LWIN * DH];
static __device__ float g_pos[(size_t)BHTOT * MEMQ  * LWIN];
static __device__ float g_att[(size_t)NBATCH * MEMQ * HIDDIM];
// pre-rounded (tf32) copies of raw inputs
static __device__ float g_qc [(size_t)NBATCH * MEMQ  * HIDDIM];
static __device__ float g_kc [(size_t)NBATCH * KVLEN * HIDDIM];
static __device__ float g_vc [(size_t)NBATCH * KVLEN * HIDDIM];
static __device__ float g_w0 [(size_t)HIDDIM * HIDDIM];
static __device__ float g_w1 [(size_t)HIDDIM * HIDDIM];
static __device__ float g_w2 [(size_t)HIDDIM * HIDDIM];
static __device__ float g_w3 [(size_t)HIDDIM * HIDDIM];

// ---------------- helpers ----------------
__device__ __forceinline__ float to_tf32(float x){
    uint32_t y;
    asm("cvt.rna.tf32.f32 %0, %1;" : "=r"(y) : "f"(x));
    return __uint_as_float(y);
}
__device__ __forceinline__ void mma_tf32(float c[4], const uint32_t a[4],
                                         uint32_t b0, uint32_t b1){
    asm("mma.sync.aligned.m16n8k8.row.col.f32.tf32.tf32.f32 "
        "{%0,%1,%2,%3}, {%4,%5,%6,%7}, {%8,%9}, {%0,%1,%2,%3};"
        : "+f"(c[0]), "+f"(c[1]), "+f"(c[2]), "+f"(c[3])
        : "r"(a[0]), "r"(a[1]), "r"(a[2]), "r"(a[3]), "r"(b0), "r"(b1));
}
__device__ __forceinline__ void cp_async16(void* sptr, const void* gptr){
    uint32_t sa = (uint32_t)__cvta_generic_to_shared(sptr);
    asm volatile("cp.async.cg.shared.global [%0], [%1], 16;\n" :: "r"(sa), "l"(gptr));
}

// ---------------- elementwise tf32 cast (float4) ----------------
__global__ void tf32_cast(const float4* __restrict__ src, float4* __restrict__ dst, int n4){
    int i = blockIdx.x * 256 + threadIdx.x;
    if (i < n4) {
        float4 v = src[i];
        v.x = to_tf32(v.x); v.y = to_tf32(v.y);
        v.z = to_tf32(v.z); v.w = to_tf32(v.w);
        dst[i] = v;
    }
}

// ---------------- pe transpose (rounded) ----------------
__global__ void transpose_pe(const float* __restrict__ pe, float* __restrict__ peT){
    int idx = blockIdx.x * 256 + threadIdx.x;
    int l = idx >> 6;
    int d = idx & 63;
    peT[idx] = to_tf32(pe[(size_t)d * LWIN + l]);
}

// ---------------- pipelined NT GEMM (operands pre-rounded tf32) ----------------
// k-slot permutation: within each 8-wide k step, thread tg's two k slots are the
// physically adjacent pair {kb+2tg, kb+2tg+1} -> float2 fragment loads.
#define GSTRIDE 36
#define GSTAGE  (128 * GSTRIDE)

__global__ __launch_bounds__(256, 2)
void gemm_nt(const float* __restrict__ A, int lda,
             const float* __restrict__ B,
             float* __restrict__ C,
             int K, int ldc, int mode, int S)
{
    extern __shared__ float sm[];

    const int tid  = threadIdx.x;
    const int warp = tid >> 5, lane = tid & 31;
    const int wm = warp >> 2, wn = warp & 3;
    const int g  = lane >> 2, tg = lane & 3;
    const int rowBase = blockIdx.x * 128;
    const int colBase = blockIdx.y * 128;

    float acc[4][4][4];
    #pragma unroll
    for (int mt = 0; mt < 4; mt++)
        #pragma unroll
        for (int nt = 0; nt < 4; nt++)
            #pragma unroll
            for (int i = 0; i < 4; i++) acc[mt][nt][i] = 0.f;

    const int niter = K >> 5;

    auto load_tiles = [&](int st, int k0){
        float* As = sm + st * (2 * GSTAGE);
        float* Bs = As + GSTAGE;
        #pragma unroll
        for (int i = 0; i < 4; i++) {
            int c = tid + i * 256;
            int row = c >> 3, ko = (c & 7) << 2;
            cp_async16(&As[row * GSTRIDE + ko],
                       A + (size_t)(rowBase + row) * lda + k0 + ko);
        }
        #pragma unroll
        for (int i = 0; i < 4; i++) {
            int c = tid + i * 256;
            int row = c >> 3, ko = (c & 7) << 2;
            cp_async16(&Bs[row * GSTRIDE + ko],
                       B + (size_t)(colBase + row) * K + k0 + ko);
        }
    };

    load_tiles(0, 0);
    asm volatile("cp.async.commit_group;\n" ::: "memory");

    for (int it = 0; it < niter; it++) {
        if (it + 1 < niter) load_tiles((it + 1) & 1, (it + 1) << 5);
        asm volatile("cp.async.commit_group;\n" ::: "memory");
        asm volatile("cp.async.wait_group 1;\n" ::: "memory");
        __syncthreads();

        const float* As = sm + (it & 1) * (2 * GSTAGE);
        const float* Bs = As + GSTAGE;

        #pragma unroll
        for (int ks = 0; ks < 4; ks++) {
            const int kb = ks * 8 + 2 * tg;         // this thread's adjacent k pair
            uint32_t a[4][4];
            #pragma unroll
            for (int mt = 0; mt < 4; mt++) {
                int r = wm * 64 + mt * 16 + g;
                float2 v0 = *reinterpret_cast<const float2*>(&As[r * GSTRIDE + kb]);
                float2 v1 = *reinterpret_cast<const float2*>(&As[(r + 8) * GSTRIDE + kb]);
                a[mt][0] = __float_as_uint(v0.x);
                a[mt][1] = __float_as_uint(v1.x);
                a[mt][2] = __float_as_uint(v0.y);
                a[mt][3] = __float_as_uint(v1.y);
            }
            #pragma unroll
            for (int nt = 0; nt < 4; nt++) {
                int j = wn * 32 + nt * 8 + g;
                float2 vb = *reinterpret_cast<const float2*>(&Bs[j * GSTRIDE + kb]);
                uint32_t b0 = __float_as_uint(vb.x);
                uint32_t b1 = __float_as_uint(vb.y);
                #pragma unroll
                for (int mt = 0; mt < 4; mt++)
                    mma_tf32(acc[mt][nt], a[mt], b0, b1);
            }
        }
        __syncthreads();
    }

    #pragma unroll
    for (int mt = 0; mt < 4; mt++) {
        int r = rowBase + wm * 64 + mt * 16 + g;
        #pragma unroll
        for (int nt = 0; nt < 4; nt++) {
            int jc = colBase + wn * 32 + nt * 8 + 2 * tg;
            if (mode == 0) {
                C[(size_t)r       * ldc + jc    ] = acc[mt][nt][0];
                C[(size_t)r       * ldc + jc + 1] = acc[mt][nt][1];
                C[(size_t)(r + 8) * ldc + jc    ] = acc[mt][nt][2];
                C[(size_t)(r + 8) * ldc + jc + 1] = acc[mt][nt][3];
            } else {
                int h = jc >> 6, d = jc & 63;
                int b1r = r / S,  s1 = r - b1r * S;
                int r2  = r + 8;
                int b2r = r2 / S, s2 = r2 - b2r * S;
                float* p0 = C + (((size_t)(b1r * NHEADS + h) * S + s1) << 6) + d;
                float* p1 = C + (((size_t)(b2r * NHEADS + h) * S + s2) << 6) + d;
                p0[0] = to_tf32(acc[mt][nt][0]);
                p0[1] = to_tf32(acc[mt][nt][1]);
                p1[0] = to_tf32(acc[mt][nt][2]);
                p1[1] = to_tf32(acc[mt][nt][3]);
            }
        }
    }
}

// ---------------- flash-style windowed attention ----------------
// 256 threads (8 warps), 128-row Q tile, 64-key tiles, cp.async fills.
// Same k-slot permutation for Q/K (QK) and P/V (PV) fragments.
__global__ __launch_bounds__(256, 2)
void attn_kernel(const float* __restrict__ gq, const float* __restrict__ gk,
                 const float* __restrict__ gv, const float* __restrict__ gpos,
                 float* __restrict__ gatt)
{
    extern __shared__ float smb[];
    float* Qs = smb;                 // 128 x 68
    float* Ks = Qs + 128*68;         // 64 x 68
    float* Ps = Ks + 64*68;          // 128 x 68
    float* Vs = Ps + 128*68;         // 64 x 72

    const int bh = blockIdx.x;
    const int m0 = blockIdx.y * QTILE;
    const int tid  = threadIdx.x;
    const int warp = tid >> 5, lane = tid & 31;
    const int g  = lane >> 2, tg = lane & 3;
    const int r0 = warp*16 + g;

    {
        const float* qb = gq + ((size_t)bh * MEMQ + m0) * DH;
        #pragma unroll
        for (int i = tid; i < 2048; i += 256) {
            int r = i >> 4, cc = (i & 15) << 2;
            cp_async16(&Qs[r*68 + cc], qb + r*DH + cc);
        }
    }

    float o[8][4];
    #pragma unroll
    for (int nt = 0; nt < 8; nt++)
        #pragma unroll
        for (int i = 0; i < 4; i++) o[nt][i] = 0.f;
    float mi0 = -1e30f, mi1 = -1e30f, li0 = 0.f, li1 = 0.f;

    const float* posr0 = gpos + ((size_t)bh * MEMQ + m0 + r0) * LWIN;
    const float* posr1 = posr0 + (size_t)8 * LWIN;

    for (int t = 0; t < 34; t++) {
        const int j0 = m0 + t * 64;
        const float* kb = gk + ((size_t)bh * KVLEN + j0) * DH;
        const float* vb = gv + ((size_t)bh * KVLEN + j0) * DH;
        __syncthreads();
        #pragma unroll
        for (int i = tid; i < 1024; i += 256) {
            int r = i >> 4, cc = (i & 15) << 2;
            cp_async16(&Ks[r*68 + cc], kb + r*DH + cc);
            cp_async16(&Vs[r*72 + cc], vb + r*DH + cc);
        }
        asm volatile("cp.async.commit_group;\n" ::: "memory");
        asm volatile("cp.async.wait_group 0;\n" ::: "memory");
        __syncthreads();

        // S = Q @ K^T (float2 fragment loads)
        float s[8][4];
        #pragma unroll
        for (int nt = 0; nt < 8; nt++)
            #pragma unroll
            for (int i = 0; i < 4; i++) s[nt][i] = 0.f;
        #pragma unroll
        for (int ks = 0; ks < 8; ks++) {
            const int kb8 = ks * 8 + 2 * tg;
            uint32_t a[4];
            {
                float2 v0 = *reinterpret_cast<const float2*>(&Qs[r0*68     + kb8]);
                float2 v1 = *reinterpret_cast<const float2*>(&Qs[(r0+8)*68 + kb8]);
                a[0] = __float_as_uint(v0.x);
                a[1] = __float_as_uint(v1.x);
                a[2] = __float_as_uint(v0.y);
                a[3] = __float_as_uint(v1.y);
            }
            #pragma unroll
            for (int nt = 0; nt < 8; nt++) {
                int j = nt*8 + g;
                float2 vb2 = *reinterpret_cast<const float2*>(&Ks[j*68 + kb8]);
                mma_tf32(s[nt], a, __float_as_uint(vb2.x), __float_as_uint(vb2.y));
            }
        }

        #pragma unroll
        for (int nt = 0; nt < 8; nt++) {
            int jj = nt*8 + 2*tg;
            int lA = t*64 + jj - r0;
            int lB = lA - 8;
            #pragma unroll
            for (int e = 0; e < 2; e++) {
                int l1 = lA + e;
                s[nt][e]     = (l1 >= 0 && l1 < LWIN)
                             ? (s[nt][e]     + __ldg(posr0 + l1)) * 0.125f : -1e30f;
                int l2 = lB + e;
                s[nt][2 + e] = (l2 >= 0 && l2 < LWIN)
                             ? (s[nt][2 + e] + __ldg(posr1 + l2)) * 0.125f : -1e30f;
            }
        }

        float mx0 = -1e30f, mx1 = -1e30f;
        #pragma unroll
        for (int nt = 0; nt < 8; nt++) {
            mx0 = fmaxf(mx0, fmaxf(s[nt][0], s[nt][1]));
            mx1 = fmaxf(mx1, fmaxf(s[nt][2], s[nt][3]));
        }
        mx0 = fmaxf(mx0, __shfl_xor_sync(0xffffffffu, mx0, 1));
        mx0 = fmaxf(mx0, __shfl_xor_sync(0xffffffffu, mx0, 2));
        mx1 = fmaxf(mx1, __shfl_xor_sync(0xffffffffu, mx1, 1));
        mx1 = fmaxf(mx1, __shfl_xor_sync(0xffffffffu, mx1, 2));
        float mn0 = fmaxf(mi0, mx0), mn1 = fmaxf(mi1, mx1);
        float al0 = __expf(mi0 - mn0), al1 = __expf(mi1 - mn1);
        float rs0 = 0.f, rs1 = 0.f;
        #pragma unroll
        for (int nt = 0; nt < 8; nt++) {
            s[nt][0] = __expf(s[nt][0] - mn0);
            s[nt][1] = __expf(s[nt][1] - mn0);
            s[nt][2] = __expf(s[nt][2] - mn1);
            s[nt][3] = __expf(s[nt][3] - mn1);
            rs0 += s[nt][0] + s[nt][1];
            rs1 += s[nt][2] + s[nt][3];
        }
        rs0 += __shfl_xor_sync(0xffffffffu, rs0, 1);
        rs0 += __shfl_xor_sync(0xffffffffu, rs0, 2);
        rs1 += __shfl_xor_sync(0xffffffffu, rs1, 1);
        rs1 += __shfl_xor_sync(0xffffffffu, rs1, 2);
        li0 = li0 * al0 + rs0;
        li1 = li1 * al1 + rs1;
        mi0 = mn0; mi1 = mn1;

        #pragma unroll
        for (int nt = 0; nt < 8; nt++) {
            o[nt][0] *= al0; o[nt][1] *= al0; o[nt][2] *= al1; o[nt][3] *= al1;
            int col = nt*8 + 2*tg;
            Ps[r0*68     + col    ] = to_tf32(s[nt][0]);
            Ps[r0*68     + col + 1] = to_tf32(s[nt][1]);
            Ps[(r0+8)*68 + col    ] = to_tf32(s[nt][2]);
            Ps[(r0+8)*68 + col + 1] = to_tf32(s[nt][3]);
        }
        __syncwarp();

        // O += P @ V (P via float2; V rows follow the same k permutation)
        #pragma unroll
        for (int ks = 0; ks < 8; ks++) {
            const int kb8 = ks * 8 + 2 * tg;
            uint32_t a[4];
            {
                float2 v0 = *reinterpret_cast<const float2*>(&Ps[r0*68     + kb8]);
                float2 v1 = *reinterpret_cast<const float2*>(&Ps[(r0+8)*68 + kb8]);
                a[0] = __float_as_uint(v0.x);
                a[1] = __float_as_uint(v1.x);
                a[2] = __float_as_uint(v0.y);
                a[3] = __float_as_uint(v1.y);
            }
            #pragma unroll
            for (int nt = 0; nt < 8; nt++) {
                uint32_t b0 = __float_as_uint(Vs[(kb8    )*72 + nt*8 + g]);
                uint32_t b1 = __float_as_uint(Vs[(kb8 + 1)*72 + nt*8 + g]);
                mma_tf32(o[nt], a, b0, b1);
            }
        }
        __syncwarp();
    }

    const float inv0 = 1.f / li0, inv1 = 1.f / li1;
    const int b = bh >> 4, h = bh & 15;
    #pragma unroll
    for (int nt = 0; nt < 8; nt++) {
        int d = nt*8 + 2*tg;
        size_t i0 = (((size_t)(b*MEMQ + (m0 + r0    )) * NHEADS + h) << 6) + d;
        size_t i1 = (((size_t)(b*MEMQ + (m0 + r0 + 8)) * NHEADS + h) << 6) + d;
        gatt[i0    ] = to_tf32(o[nt][0] * inv0);
        gatt[i0 + 1] = to_tf32(o[nt][1] * inv0);
        gatt[i1    ] = to_tf32(o[nt][2] * inv1);
        gatt[i1 + 1] = to_tf32(o[nt][3] * inv1);
    }
}

// ---------------- launch ----------------
extern "C" void kernel_launch(void* const* d_in, const int* in_sizes, int n_in,
                              void* d_out, int out_size)
{
    const float* query = (const float*)d_in[0];
    const float* key   = (const float*)d_in[1];
    const float* value = (const float*)d_in[2];
    const float* keype = (const float*)d_in[3];
    const float* Wq    = (const float*)d_in[4];
    const float* Wk    = (const float*)d_in[5];
    const float* Wv    = (const float*)d_in[6];
    const float* Wo    = (const float*)d_in[7];
    float* out = (float*)d_out;

    float *pq, *pk, *pv, *ppeT, *ppos, *patt;
    float *pqc, *pkc, *pvc, *pw0, *pw1, *pw2, *pw3;
    cudaGetSymbolAddress((void**)&pq,   g_q);
    cudaGetSymbolAddress((void**)&pk,   g_k);
    cudaGetSymbolAddress((void**)&pv,   g_v);
    cudaGetSymbolAddress((void**)&ppeT, g_peT);
    cudaGetSymbolAddress((void**)&ppos, g_pos);
    cudaGetSymbolAddress((void**)&patt, g_att);
    cudaGetSymbolAddress((void**)&pqc,  g_qc);
    cudaGetSymbolAddress((void**)&pkc,  g_kc);
    cudaGetSymbolAddress((void**)&pvc,  g_vc);
    cudaGetSymbolAddress((void**)&pw0,  g_w0);
    cudaGetSymbolAddress((void**)&pw1,  g_w1);
    cudaGetSymbolAddress((void**)&pw2,  g_w2);
    cudaGetSymbolAddress((void**)&pw3,  g_w3);

    const int gemm_smem = 2 * 2 * GSTAGE * 4;                       // 73728 B
    const int attn_smem = (128*68 + 64*68 + 128*68 + 64*72) * 4;    // 105472 B
    cudaFuncSetAttribute(gemm_nt, cudaFuncAttributeMaxDynamicSharedMemorySize, gemm_smem);
    cudaFuncSetAttribute(attn_kernel, cudaFuncAttributeMaxDynamicSharedMemorySize, attn_smem);

    const int nq4 = NBATCH * MEMQ  * HIDDIM / 4;
    const int nk4 = NBATCH * KVLEN * HIDDIM / 4;
    const int nw4 = HIDDIM * HIDDIM / 4;
    tf32_cast<<<(nq4 + 255) / 256, 256>>>((const float4*)query, (float4*)pqc, nq4);
    tf32_cast<<<(nk4 + 255) / 256, 256>>>((const float4*)key,   (float4*)pkc, nk4);
    tf32_cast<<<(nk4 + 255) / 256, 256>>>((const float4*)value, (float4*)pvc, nk4);
    tf32_cast<<<(nw4 + 255) / 256, 256>>>((const float4*)Wq, (float4*)pw0, nw4);
    tf32_cast<<<(nw4 + 255) / 256, 256>>>((const float4*)Wk, (float4*)pw1, nw4);
    tf32_cast<<<(nw4 + 255) / 256, 256>>>((const float4*)Wv, (float4*)pw2, nw4);
    tf32_cast<<<(nw4 + 255) / 256, 256>>>((const float4*)Wo, (float4*)pw3, nw4);
    transpose_pe<<<512, 256>>>(keype, ppeT);

    gemm_nt<<<dim3(32, 8),  256, gemm_smem>>>(pqc, HIDDIM, pw0, pq, HIDDIM, 0, 1, MEMQ);
    gemm_nt<<<dim3(160, 8), 256, gemm_smem>>>(pkc, HIDDIM, pw1, pk, HIDDIM, 0, 1, KVLEN);
    gemm_nt<<<dim3(160, 8), 256, gemm_smem>>>(pvc, HIDDIM, pw2, pv, HIDDIM, 0, 1, KVLEN);
    gemm_nt<<<dim3(512, 16), 256, gemm_smem>>>(pq, DH, ppeT, ppos, DH, LWIN, 0, 0);
    attn_kernel<<<dim3(BHTOT, 4), 256, attn_smem>>>(pq, pk, pv, ppos, patt);
    gemm_nt<<<dim3(32, 8), 256, gemm_smem>>>(patt, HIDDIM, pw3, out, HIDDIM, HIDDIM, 0, 0);
}

// round 9
// speedup vs baseline: 1.2225x; 1.2225x over previous
#include <cuda_runtime.h>
#include <cstdint>
#include <cstddef>

#define HIDDIM 1024
#define NHEADS 16
#define MEMQ   512
#define LWIN   2048
#define KVLEN  2560
#define DH     64
#define NBATCH 8
#define BHTOT  128
#define QTILE  128

// ---------------- scratch ----------------
static __device__ float g_q  [(size_t)BHTOT * MEMQ  * DH];
static __device__ float g_k  [(size_t)BHTOT * KVLEN * DH];
static __device__ float g_v  [(size_t)BHTOT * KVLEN * DH];
static __device__ float g_peT[(size_t)LWIN * DH];
static __device__ float g_pos[(size_t)BHTOT * MEMQ  * LWIN];
static __device__ float g_att[(size_t)NBATCH * MEMQ * HIDDIM];
static __device__ float g_w0 [(size_t)HIDDIM * HIDDIM];
static __device__ float g_w1 [(size_t)HIDDIM * HIDDIM];
static __device__ float g_w2 [(size_t)HIDDIM * HIDDIM];
static __device__ float g_w3 [(size_t)HIDDIM * HIDDIM];

// ---------------- helpers ----------------
__device__ __forceinline__ float to_tf32(float x){
    uint32_t y;
    asm("cvt.rna.tf32.f32 %0, %1;" : "=r"(y) : "f"(x));
    return __uint_as_float(y);
}
__device__ __forceinline__ uint32_t tf32u(float x){
    uint32_t y;
    asm("cvt.rna.tf32.f32 %0, %1;" : "=r"(y) : "f"(x));
    return y;
}
__device__ __forceinline__ void mma_tf32(float c[4], const uint32_t a[4],
                                         uint32_t b0, uint32_t b1){
    asm("mma.sync.aligned.m16n8k8.row.col.f32.tf32.tf32.f32 "
        "{%0,%1,%2,%3}, {%4,%5,%6,%7}, {%8,%9}, {%0,%1,%2,%3};"
        : "+f"(c[0]), "+f"(c[1]), "+f"(c[2]), "+f"(c[3])
        : "r"(a[0]), "r"(a[1]), "r"(a[2]), "r"(a[3]), "r"(b0), "r"(b1));
}
__device__ __forceinline__ void cp_async16(void* sptr, const void* gptr){
    uint32_t sa = (uint32_t)__cvta_generic_to_shared(sptr);
    asm volatile("cp.async.cg.shared.global [%0], [%1], 16;\n" :: "r"(sa), "l"(gptr));
}

// ---------------- elementwise tf32 cast (float4) ----------------
__global__ void tf32_cast(const float4* __restrict__ src, float4* __restrict__ dst, int n4){
    int i = blockIdx.x * 256 + threadIdx.x;
    if (i < n4) {
        float4 v = src[i];
        v.x = to_tf32(v.x); v.y = to_tf32(v.y);
        v.z = to_tf32(v.z); v.w = to_tf32(v.w);
        dst[i] = v;
    }
}

// ---------------- pe transpose (rounded) ----------------
__global__ void transpose_pe(const float* __restrict__ pe, float* __restrict__ peT){
    int idx = blockIdx.x * 256 + threadIdx.x;
    int l = idx >> 6;
    int d = idx & 63;
    peT[idx] = to_tf32(pe[(size_t)d * LWIN + l]);
}

// ---------------- pipelined NT GEMM ----------------
// A: raw fp32 (cvt.rna applied on fragment load; idempotent if pre-rounded).
// B: pre-rounded tf32. R6-proven fragment pattern.
#define GSTRIDE 36
#define GSTAGE  (128 * GSTRIDE)

__global__ __launch_bounds__(256, 2)
void gemm_nt(const float* __restrict__ A, int lda,
             const float* __restrict__ B,
             float* __restrict__ C,
             int K, int ldc, int mode, int S)
{
    extern __shared__ float sm[];

    const int tid  = threadIdx.x;
    const int warp = tid >> 5, lane = tid & 31;
    const int wm = warp >> 2, wn = warp & 3;
    const int g  = lane >> 2, tg = lane & 3;
    const int rowBase = blockIdx.x * 128;
    const int colBase = blockIdx.y * 128;

    float acc[4][4][4];
    #pragma unroll
    for (int mt = 0; mt < 4; mt++)
        #pragma unroll
        for (int nt = 0; nt < 4; nt++)
            #pragma unroll
            for (int i = 0; i < 4; i++) acc[mt][nt][i] = 0.f;

    const int niter = K >> 5;

    auto load_tiles = [&](int st, int k0){
        float* As = sm + st * (2 * GSTAGE);
        float* Bs = As + GSTAGE;
        #pragma unroll
        for (int i = 0; i < 4; i++) {
            int c = tid + i * 256;
            int row = c >> 3, ko = (c & 7) << 2;
            cp_async16(&As[row * GSTRIDE + ko],
                       A + (size_t)(rowBase + row) * lda + k0 + ko);
        }
        #pragma unroll
        for (int i = 0; i < 4; i++) {
            int c = tid + i * 256;
            int row = c >> 3, ko = (c & 7) << 2;
            cp_async16(&Bs[row * GSTRIDE + ko],
                       B + (size_t)(colBase + row) * K + k0 + ko);
        }
    };

    load_tiles(0, 0);
    asm volatile("cp.async.commit_group;\n" ::: "memory");

    for (int it = 0; it < niter; it++) {
        if (it + 1 < niter) load_tiles((it + 1) & 1, (it + 1) << 5);
        asm volatile("cp.async.commit_group;\n" ::: "memory");
        asm volatile("cp.async.wait_group 1;\n" ::: "memory");
        __syncthreads();

        const float* As = sm + (it & 1) * (2 * GSTAGE);
        const float* Bs = As + GSTAGE;

        #pragma unroll
        for (int ks = 0; ks < 4; ks++) {
            const int kb = ks * 8;
            uint32_t a[4][4];
            #pragma unroll
            for (int mt = 0; mt < 4; mt++) {
                int r = wm * 64 + mt * 16 + g;
                a[mt][0] = tf32u(As[r * GSTRIDE       + kb     + tg]);
                a[mt][1] = tf32u(As[(r + 8) * GSTRIDE + kb     + tg]);
                a[mt][2] = tf32u(As[r * GSTRIDE       + kb + 4 + tg]);
                a[mt][3] = tf32u(As[(r + 8) * GSTRIDE + kb + 4 + tg]);
            }
            #pragma unroll
            for (int nt = 0; nt < 4; nt++) {
                int j = wn * 32 + nt * 8 + g;
                uint32_t b0 = __float_as_uint(Bs[j * GSTRIDE + kb     + tg]);
                uint32_t b1 = __float_as_uint(Bs[j * GSTRIDE + kb + 4 + tg]);
                #pragma unroll
                for (int mt = 0; mt < 4; mt++)
                    mma_tf32(acc[mt][nt], a[mt], b0, b1);
            }
        }
        __syncthreads();
    }

    #pragma unroll
    for (int mt = 0; mt < 4; mt++) {
        int r = rowBase + wm * 64 + mt * 16 + g;
        #pragma unroll
        for (int nt = 0; nt < 4; nt++) {
            int jc = colBase + wn * 32 + nt * 8 + 2 * tg;
            if (mode == 0) {
                C[(size_t)r       * ldc + jc    ] = acc[mt][nt][0];
                C[(size_t)r       * ldc + jc + 1] = acc[mt][nt][1];
                C[(size_t)(r + 8) * ldc + jc    ] = acc[mt][nt][2];
                C[(size_t)(r + 8) * ldc + jc + 1] = acc[mt][nt][3];
            } else {
                int h = jc >> 6, d = jc & 63;
                int b1r = r / S,  s1 = r - b1r * S;
                int r2  = r + 8;
                int b2r = r2 / S, s2 = r2 - b2r * S;
                float* p0 = C + (((size_t)(b1r * NHEADS + h) * S + s1) << 6) + d;
                float* p1 = C + (((size_t)(b2r * NHEADS + h) * S + s2) << 6) + d;
                p0[0] = to_tf32(acc[mt][nt][0]);
                p0[1] = to_tf32(acc[mt][nt][1]);
                p1[0] = to_tf32(acc[mt][nt][2]);
                p1[1] = to_tf32(acc[mt][nt][3]);
            }
        }
    }
}

// ---------------- flash-style windowed attention ----------------
// 256 threads, 128-row Q tile. Q fragments hoisted to registers;
// K/V double-buffered (2 stages), cp.async prefetch overlaps compute.
// smem floats: stage s at s*8960: Ks 64x68 then Vs 64x72; Ps at 17920 (128x68).
__global__ __launch_bounds__(256, 2)
void attn_kernel(const float* __restrict__ gq, const float* __restrict__ gk,
                 const float* __restrict__ gv, const float* __restrict__ gpos,
                 float* __restrict__ gatt)
{
    extern __shared__ float smb[];
    float* Ps = smb + 17920;         // 128 x 68 (also Q staging area)

    const int bh = blockIdx.x;
    const int m0 = blockIdx.y * QTILE;
    const int tid  = threadIdx.x;
    const int warp = tid >> 5, lane = tid & 31;
    const int g  = lane >> 2, tg = lane & 3;
    const int r0 = warp*16 + g;

    // stage Q into Ps region
    {
        const float* qb = gq + ((size_t)bh * MEMQ + m0) * DH;
        #pragma unroll
        for (int i = tid; i < 2048; i += 256) {
            int r = i >> 4, cc = (i & 15) << 2;
            cp_async16(&Ps[r*68 + cc], qb + r*DH + cc);
        }
    }
    asm volatile("cp.async.commit_group;\n" ::: "memory");

    // prefetch KV tile 0 into stage 0
    {
        const float* kb = gk + ((size_t)bh * KVLEN + m0) * DH;
        const float* vb = gv + ((size_t)bh * KVLEN + m0) * DH;
        float* Ks = smb;
        float* Vs = smb + 4352;
        #pragma unroll
        for (int i = tid; i < 1024; i += 256) {
            int r = i >> 4, cc = (i & 15) << 2;
            cp_async16(&Ks[r*68 + cc], kb + r*DH + cc);
            cp_async16(&Vs[r*72 + cc], vb + r*DH + cc);
        }
    }
    asm volatile("cp.async.commit_group;\n" ::: "memory");
    asm volatile("cp.async.wait_group 1;\n" ::: "memory");   // Q staged
    __syncthreads();

    // hoist Q fragments to registers (loop-invariant)
    uint32_t qf[8][4];
    #pragma unroll
    for (int ks = 0; ks < 8; ks++) {
        const int kb8 = ks * 8;
        qf[ks][0] = __float_as_uint(Ps[r0*68     + kb8     + tg]);
        qf[ks][1] = __float_as_uint(Ps[(r0+8)*68 + kb8     + tg]);
        qf[ks][2] = __float_as_uint(Ps[r0*68     + kb8 + 4 + tg]);
        qf[ks][3] = __float_as_uint(Ps[(r0+8)*68 + kb8 + 4 + tg]);
    }

    float o[8][4];
    #pragma unroll
    for (int nt = 0; nt < 8; nt++)
        #pragma unroll
        for (int i = 0; i < 4; i++) o[nt][i] = 0.f;
    float mi0 = -1e30f, mi1 = -1e30f, li0 = 0.f, li1 = 0.f;

    const float* posr0 = gpos + ((size_t)bh * MEMQ + m0 + r0) * LWIN;
    const float* posr1 = posr0 + (size_t)8 * LWIN;

    for (int t = 0; t < 34; t++) {
        __syncthreads();   // all threads done with the stage about to be overwritten
        if (t + 1 < 34) {
            const int j1 = m0 + (t + 1) * 64;
            const float* kb = gk + ((size_t)bh * KVLEN + j1) * DH;
            const float* vb = gv + ((size_t)bh * KVLEN + j1) * DH;
            float* Kn = smb + ((t + 1) & 1) * 8960;
            float* Vn = Kn + 4352;
            #pragma unroll
            for (int i = tid; i < 1024; i += 256) {
                int r = i >> 4, cc = (i & 15) << 2;
                cp_async16(&Kn[r*68 + cc], kb + r*DH + cc);
                cp_async16(&Vn[r*72 + cc], vb + r*DH + cc);
            }
            asm volatile("cp.async.commit_group;\n" ::: "memory");
            asm volatile("cp.async.wait_group 1;\n" ::: "memory");  // tile t done
        } else {
            asm volatile("cp.async.wait_group 0;\n" ::: "memory");
        }
        __syncthreads();   // tile t visible to all

        const float* Ks = smb + (t & 1) * 8960;
        const float* Vs = Ks + 4352;

        // S = Q @ K^T
        float s[8][4];
        #pragma unroll
        for (int nt = 0; nt < 8; nt++)
            #pragma unroll
            for (int i = 0; i < 4; i++) s[nt][i] = 0.f;
        #pragma unroll
        for (int ks = 0; ks < 8; ks++) {
            const int kb8 = ks * 8;
            #pragma unroll
            for (int nt = 0; nt < 8; nt++) {
                int j = nt*8 + g;
                uint32_t b0 = __float_as_uint(Ks[j*68 + kb8     + tg]);
                uint32_t b1 = __float_as_uint(Ks[j*68 + kb8 + 4 + tg]);
                mma_tf32(s[nt], qf[ks], b0, b1);
            }
        }

        // bias + window mask + scale
        #pragma unroll
        for (int nt = 0; nt < 8; nt++) {
            int jj = nt*8 + 2*tg;
            int lA = t*64 + jj - r0;
            int lB = lA - 8;
            #pragma unroll
            for (int e = 0; e < 2; e++) {
                int l1 = lA + e;
                s[nt][e]     = (l1 >= 0 && l1 < LWIN)
                             ? (s[nt][e]     + __ldg(posr0 + l1)) * 0.125f : -1e30f;
                int l2 = lB + e;
                s[nt][2 + e] = (l2 >= 0 && l2 < LWIN)
                             ? (s[nt][2 + e] + __ldg(posr1 + l2)) * 0.125f : -1e30f;
            }
        }

        // online softmax
        float mx0 = -1e30f, mx1 = -1e30f;
        #pragma unroll
        for (int nt = 0; nt < 8; nt++) {
            mx0 = fmaxf(mx0, fmaxf(s[nt][0], s[nt][1]));
            mx1 = fmaxf(mx1, fmaxf(s[nt][2], s[nt][3]));
        }
        mx0 = fmaxf(mx0, __shfl_xor_sync(0xffffffffu, mx0, 1));
        mx0 = fmaxf(mx0, __shfl_xor_sync(0xffffffffu, mx0, 2));
        mx1 = fmaxf(mx1, __shfl_xor_sync(0xffffffffu, mx1, 1));
        mx1 = fmaxf(mx1, __shfl_xor_sync(0xffffffffu, mx1, 2));
        float mn0 = fmaxf(mi0, mx0), mn1 = fmaxf(mi1, mx1);
        float al0 = __expf(mi0 - mn0), al1 = __expf(mi1 - mn1);
        float rs0 = 0.f, rs1 = 0.f;
        #pragma unroll
        for (int nt = 0; nt < 8; nt++) {
            s[nt][0] = __expf(s[nt][0] - mn0);
            s[nt][1] = __expf(s[nt][1] - mn0);
            s[nt][2] = __expf(s[nt][2] - mn1);
            s[nt][3] = __expf(s[nt][3] - mn1);
            rs0 += s[nt][0] + s[nt][1];
            rs1 += s[nt][2] + s[nt][3];
        }
        rs0 += __shfl_xor_sync(0xffffffffu, rs0, 1);
        rs0 += __shfl_xor_sync(0xffffffffu, rs0, 2);
        rs1 += __shfl_xor_sync(0xffffffffu, rs1, 1);
        rs1 += __shfl_xor_sync(0xffffffffu, rs1, 2);
        li0 = li0 * al0 + rs0;
        li1 = li1 * al1 + rs1;
        mi0 = mn0; mi1 = mn1;

        // rescale O, stage P (tf32)
        #pragma unroll
        for (int nt = 0; nt < 8; nt++) {
            o[nt][0] *= al0; o[nt][1] *= al0; o[nt][2] *= al1; o[nt][3] *= al1;
            int col = nt*8 + 2*tg;
            Ps[r0*68     + col    ] = to_tf32(s[nt][0]);
            Ps[r0*68     + col + 1] = to_tf32(s[nt][1]);
            Ps[(r0+8)*68 + col    ] = to_tf32(s[nt][2]);
            Ps[(r0+8)*68 + col + 1] = to_tf32(s[nt][3]);
        }
        __syncwarp();

        // O += P @ V
        #pragma unroll
        for (int ks = 0; ks < 8; ks++) {
            const int kb8 = ks * 8;
            uint32_t a[4];
            a[0] = __float_as_uint(Ps[r0*68     + kb8     + tg]);
            a[1] = __float_as_uint(Ps[(r0+8)*68 + kb8     + tg]);
            a[2] = __float_as_uint(Ps[r0*68     + kb8 + 4 + tg]);
            a[3] = __float_as_uint(Ps[(r0+8)*68 + kb8 + 4 + tg]);
            #pragma unroll
            for (int nt = 0; nt < 8; nt++) {
                uint32_t b0 = __float_as_uint(Vs[(kb8     + tg)*72 + nt*8 + g]);
                uint32_t b1 = __float_as_uint(Vs[(kb8 + 4 + tg)*72 + nt*8 + g]);
                mma_tf32(o[nt], a, b0, b1);
            }
        }
        __syncwarp();
    }

    // normalize + write rounded [B][M][H][D]
    const float inv0 = 1.f / li0, inv1 = 1.f / li1;
    const int b = bh >> 4, h = bh & 15;
    #pragma unroll
    for (int nt = 0; nt < 8; nt++) {
        int d = nt*8 + 2*tg;
        size_t i0 = (((size_t)(b*MEMQ + (m0 + r0    )) * NHEADS + h) << 6) + d;
        size_t i1 = (((size_t)(b*MEMQ + (m0 + r0 + 8)) * NHEADS + h) << 6) + d;
        gatt[i0    ] = to_tf32(o[nt][0] * inv0);
        gatt[i0 + 1] = to_tf32(o[nt][1] * inv0);
        gatt[i1    ] = to_tf32(o[nt][2] * inv1);
        gatt[i1 + 1] = to_tf32(o[nt][3] * inv1);
    }
}

// ---------------- launch ----------------
extern "C" void kernel_launch(void* const* d_in, const int* in_sizes, int n_in,
                              void* d_out, int out_size)
{
    const float* query = (const float*)d_in[0];
    const float* key   = (const float*)d_in[1];
    const float* value = (const float*)d_in[2];
    const float* keype = (const float*)d_in[3];
    const float* Wq    = (const float*)d_in[4];
    const float* Wk    = (const float*)d_in[5];
    const float* Wv    = (const float*)d_in[6];
    const float* Wo    = (const float*)d_in[7];
    float* out = (float*)d_out;

    float *pq, *pk, *pv, *ppeT, *ppos, *patt;
    float *pw0, *pw1, *pw2, *pw3;
    cudaGetSymbolAddress((void**)&pq,   g_q);
    cudaGetSymbolAddress((void**)&pk,   g_k);
    cudaGetSymbolAddress((void**)&pv,   g_v);
    cudaGetSymbolAddress((void**)&ppeT, g_peT);
    cudaGetSymbolAddress((void**)&ppos, g_pos);
    cudaGetSymbolAddress((void**)&patt, g_att);
    cudaGetSymbolAddress((void**)&pw0,  g_w0);
    cudaGetSymbolAddress((void**)&pw1,  g_w1);
    cudaGetSymbolAddress((void**)&pw2,  g_w2);
    cudaGetSymbolAddress((void**)&pw3,  g_w3);

    const int gemm_smem = 2 * 2 * GSTAGE * 4;                 // 73728 B
    const int attn_smem = (2 * 8960 + 128 * 68) * 4;          // 106496 B
    cudaFuncSetAttribute(gemm_nt, cudaFuncAttributeMaxDynamicSharedMemorySize, gemm_smem);
    cudaFuncSetAttribute(attn_kernel, cudaFuncAttributeMaxDynamicSharedMemorySize, attn_smem);

    const int nw4 = HIDDIM * HIDDIM / 4;
    tf32_cast<<<(nw4 + 255) / 256, 256>>>((const float4*)Wq, (float4*)pw0, nw4);
    tf32_cast<<<(nw4 + 255) / 256, 256>>>((const float4*)Wk, (float4*)pw1, nw4);
    tf32_cast<<<(nw4 + 255) / 256, 256>>>((const float4*)Wv, (float4*)pw2, nw4);
    tf32_cast<<<(nw4 + 255) / 256, 256>>>((const float4*)Wo, (float4*)pw3, nw4);
    transpose_pe<<<512, 256>>>(keype, ppeT);

    gemm_nt<<<dim3(32, 8),  256, gemm_smem>>>(query, HIDDIM, pw0, pq, HIDDIM, 0, 1, MEMQ);
    gemm_nt<<<dim3(160, 8), 256, gemm_smem>>>(key,   HIDDIM, pw1, pk, HIDDIM, 0, 1, KVLEN);
    gemm_nt<<<dim3(160, 8), 256, gemm_smem>>>(value, HIDDIM, pw2, pv, HIDDIM, 0, 1, KVLEN);
    gemm_nt<<<dim3(512, 16), 256, gemm_smem>>>(pq, DH, ppeT, ppos, DH, LWIN, 0, 0);
    attn_kernel<<<dim3(BHTOT, 4), 256, attn_smem>>>(pq, pk, pv, ppos, patt);
    gemm_nt<<<dim3(32, 8), 256, gemm_smem>>>(patt, HIDDIM, pw3, out, HIDDIM, HIDDIM, 0, 0);
}